// round 2
// baseline (speedup 1.0000x reference)
#include <cuda_runtime.h>
#include <math.h>

#define NB 8
#define NC 64
#define NH 256
#define NW 256
#define NHW (NH * NW)      // 65536
#define NBHW (NB * NHW)    // 524288

// Scratch: 2 MB each, static device allocations (no cudaMalloc).
__device__ float g_gray[NBHW];
__device__ float g_dog[NBHW];

// ---------------------------------------------------------------------------
// K1: gray = mean over 64 channels. One thread per float4 of (b,h,w).
// x is streamed (evict-first): it will not fit in L2 and is re-read by K3
// from HBM anyway; keep L2 for the gray/dog scratch.
// ---------------------------------------------------------------------------
__global__ void __launch_bounds__(256) gray_kernel(const float* __restrict__ x) {
    int idx = blockIdx.x * 256 + threadIdx.x;      // [0, NBHW/4)
    int b   = idx >> 14;                            // NHW/4 = 16384
    int hw4 = idx & 16383;
    const float4* xp = reinterpret_cast<const float4*>(x)
                       + ((size_t)b * NC) * 16384 + hw4;
    float sx = 0.f, sy = 0.f, sz = 0.f, sw = 0.f;
    #pragma unroll 8
    for (int c = 0; c < NC; ++c) {
        float4 v = __ldcs(&xp[(size_t)c * 16384]);
        sx += v.x; sy += v.y; sz += v.z; sw += v.w;
    }
    const float inv = 1.0f / 64.0f;
    float4 o;
    o.x = sx * inv; o.y = sy * inv; o.z = sz * inv; o.w = sw * inv;
    reinterpret_cast<float4*>(g_gray)[idx] = o;
}

// ---------------------------------------------------------------------------
// K2: dog = conv5x5(gray, gk1 - gk2) with zero padding.
// Weights computed per-block with expf (matches reference f32 semantics,
// avoids per-thread MUFU blowup). Reads are L2 hits (gray = 2 MB).
// ---------------------------------------------------------------------------
__global__ void __launch_bounds__(256) dog_kernel() {
    __shared__ float wd[25];
    if (threadIdx.x < 25) {
        int di = (int)(threadIdx.x / 5) - 2;
        int dj = (int)(threadIdx.x % 5) - 2;
        float d2 = (float)(di * di + dj * dj);
        float s1 = 0.f, s2 = 0.f;
        for (int i = -2; i <= 2; ++i)
            for (int j = -2; j <= 2; ++j) {
                float dd = (float)(i * i + j * j);
                s1 += expf(-dd * 0.5f);    // sigma1 = 1.0 -> /(2*1^2)
                s2 += expf(-dd * 0.125f);  // sigma2 = 2.0 -> /(2*2^2)
            }
        wd[threadIdx.x] = expf(-d2 * 0.5f) / s1 - expf(-d2 * 0.125f) / s2;
    }
    __syncthreads();

    int idx = blockIdx.x * 256 + threadIdx.x;  // [0, NBHW)
    int b  = idx >> 16;
    int hw = idx & 65535;
    int h  = hw >> 8;
    int w  = hw & 255;
    const float* g = g_gray + (b << 16);
    float acc = 0.f;
    #pragma unroll
    for (int i = 0; i < 5; ++i) {
        int hh = h + i - 2;
        if ((unsigned)hh >= NH) continue;
        const float* gr = g + hh * NW;
        #pragma unroll
        for (int j = 0; j < 5; ++j) {
            int ww = w + j - 2;
            if ((unsigned)ww < NW) acc += wd[i * 5 + j] * gr[ww];
        }
    }
    g_dog[idx] = acc;
}

// ---------------------------------------------------------------------------
// K3: att = sigmoid(gate_w * sqrt(gx^2+gy^2+1e-6) + gate_b); out = x*(1+att).
// One thread per float4 pixel; att computed once, reused across 64 channels.
// Sobel over dog with zero padding (dog = 0 outside grid, per reference).
// x reads and out writes are streamed (no reuse).
// ---------------------------------------------------------------------------
__global__ void __launch_bounds__(256) out_kernel(const float* __restrict__ x,
                                                  const float* __restrict__ gw,
                                                  const float* __restrict__ gb,
                                                  float* __restrict__ out) {
    int idx = blockIdx.x * 256 + threadIdx.x;  // [0, NBHW/4)
    int b   = idx >> 14;
    int hw4 = idx & 16383;
    int h   = hw4 >> 6;
    int w0  = (hw4 & 63) << 2;

    const float* dg = g_dog + (b << 16);
    float d[3][6];
    #pragma unroll
    for (int r = 0; r < 3; ++r) {
        int hh = h - 1 + r;
        bool hok = (unsigned)hh < NH;
        #pragma unroll
        for (int k = 0; k < 6; ++k) {
            int ww = w0 - 1 + k;
            d[r][k] = (hok && (unsigned)ww < NW) ? dg[hh * NW + ww] : 0.f;
        }
    }

    float gwv = gw[0], gbv = gb[0];
    float att[4];
    #pragma unroll
    for (int p = 0; p < 4; ++p) {
        float gx = (d[0][p + 2] - d[0][p]) + 2.f * (d[1][p + 2] - d[1][p])
                 + (d[2][p + 2] - d[2][p]);
        float gy = (d[2][p] + 2.f * d[2][p + 1] + d[2][p + 2])
                 - (d[0][p] + 2.f * d[0][p + 1] + d[0][p + 2]);
        float mag = sqrtf(gx * gx + gy * gy + 1e-6f);
        float z = fmaf(mag, gwv, gbv);
        att[p] = 1.f + 1.f / (1.f + expf(-z));   // 1 + ALPHA * sigmoid(z)
    }

    const float4* xp = reinterpret_cast<const float4*>(x)
                       + ((size_t)b * NC) * 16384 + hw4;
    float4* op = reinterpret_cast<float4*>(out)
                 + ((size_t)b * NC) * 16384 + hw4;
    #pragma unroll 4
    for (int c = 0; c < NC; ++c) {
        float4 v = __ldcs(&xp[(size_t)c * 16384]);
        v.x *= att[0]; v.y *= att[1]; v.z *= att[2]; v.w *= att[3];
        __stcs(&op[(size_t)c * 16384], v);
    }
}

// ---------------------------------------------------------------------------
extern "C" void kernel_launch(void* const* d_in, const int* in_sizes, int n_in,
                              void* d_out, int out_size) {
    const float* x  = (const float*)d_in[0];
    const float* gw = (const float*)d_in[1];
    const float* gb = (const float*)d_in[2];
    float* out = (float*)d_out;

    gray_kernel<<<512, 256>>>(x);
    dog_kernel<<<2048, 256>>>();
    out_kernel<<<512, 256>>>(x, gw, gb, out);
}